// round 1
// baseline (speedup 1.0000x reference)
#include <cuda_runtime.h>
#include <cuda_bf16.h>
#include <math_constants.h>

// Problem constants
#define B_   2
#define L_   2048
#define D_   1024
#define H_   16
#define HD_  64
#define NTOK (B_ * L_)          // 4096
#define SCALE 0.125f            // HD^-0.5

// Scratch for projected Q/K/V: [B*L, D] each, feature index = h*64+hd
__device__ float g_Q[NTOK * D_];
__device__ float g_K[NTOK * D_];
__device__ float g_V[NTOK * D_];

// ---------------------------------------------------------------------------
// Projection GEMM: Y[m,n] = sum_k X[m,k] * W[n,k]   (M=4096, N=1024, K=1024)
// 128x128 tile, BK=16, 256 threads, 8x8 register micro-tile.
// blockIdx.z selects which of {q,k,v} projection.
// ---------------------------------------------------------------------------
#define GBM 128
#define GBN 128
#define GBK 16

__global__ void __launch_bounds__(256, 2)
proj_gemm(const float* __restrict__ q, const float* __restrict__ k,
          const float* __restrict__ v, const float* __restrict__ Wq,
          const float* __restrict__ Wk, const float* __restrict__ Wv)
{
    const int which = blockIdx.z;
    const float* X = (which == 0) ? q : (which == 1) ? k : v;
    const float* W = (which == 0) ? Wq : (which == 1) ? Wk : Wv;
    float* Y = (which == 0) ? g_Q : (which == 1) ? g_K : g_V;

    __shared__ float As[GBK][GBM + 4];   // +4 keeps rows 16B-aligned
    __shared__ float Bs[GBK][GBN + 4];

    const int tid = threadIdx.x;
    const int bm = blockIdx.y * GBM;
    const int bn = blockIdx.x * GBN;

    const int tm = (tid >> 4) << 3;      // 0..120
    const int tn = (tid & 15) << 3;      // 0..120

    float acc[8][8];
    #pragma unroll
    for (int i = 0; i < 8; i++)
        #pragma unroll
        for (int j = 0; j < 8; j++) acc[i][j] = 0.f;

    for (int k0 = 0; k0 < D_; k0 += GBK) {
        // Load 128x16 tiles of X and W (transposed into smem as [k][m])
        #pragma unroll
        for (int p = 0; p < 2; p++) {
            int idx = tid + p * 256;             // 0..511 float4 slots
            int row = idx >> 2;                  // 0..127
            int kc  = (idx & 3) << 2;            // 0,4,8,12
            float4 xv = *(const float4*)(X + (size_t)(bm + row) * D_ + k0 + kc);
            As[kc + 0][row] = xv.x; As[kc + 1][row] = xv.y;
            As[kc + 2][row] = xv.z; As[kc + 3][row] = xv.w;
            float4 wv = *(const float4*)(W + (size_t)(bn + row) * D_ + k0 + kc);
            Bs[kc + 0][row] = wv.x; Bs[kc + 1][row] = wv.y;
            Bs[kc + 2][row] = wv.z; Bs[kc + 3][row] = wv.w;
        }
        __syncthreads();

        #pragma unroll
        for (int kk = 0; kk < GBK; kk++) {
            float a[8], b[8];
            #pragma unroll
            for (int i = 0; i < 8; i += 4) {
                float4 t = *(const float4*)(&As[kk][tm + i]);
                a[i] = t.x; a[i+1] = t.y; a[i+2] = t.z; a[i+3] = t.w;
            }
            #pragma unroll
            for (int j = 0; j < 8; j += 4) {
                float4 t = *(const float4*)(&Bs[kk][tn + j]);
                b[j] = t.x; b[j+1] = t.y; b[j+2] = t.z; b[j+3] = t.w;
            }
            #pragma unroll
            for (int i = 0; i < 8; i++)
                #pragma unroll
                for (int j = 0; j < 8; j++)
                    acc[i][j] = fmaf(a[i], b[j], acc[i][j]);
        }
        __syncthreads();
    }

    #pragma unroll
    for (int i = 0; i < 8; i++) {
        float* yrow = Y + (size_t)(bm + tm + i) * D_ + bn + tn;
        #pragma unroll
        for (int j = 0; j < 8; j += 4) {
            float4 t = make_float4(acc[i][j], acc[i][j+1], acc[i][j+2], acc[i][j+3]);
            *(float4*)(yrow + j) = t;
        }
    }
}

// ---------------------------------------------------------------------------
// Flash attention with relative bias: score = (Q.K)*scale + (q_idx - kv_idx)
// One thread owns one query row. Q row / output acc / tile scores in registers.
// K/V tiles (32 x 64) staged in smem; compute reads are warp-broadcast.
// grid = (L/128, H, B), block = 128.
// ---------------------------------------------------------------------------
#define BKV 32

__global__ void __launch_bounds__(128)
flash_attn(float* __restrict__ out)
{
    const int b = blockIdx.z;
    const int h = blockIdx.y;
    const int q_idx = blockIdx.x * 128 + threadIdx.x;   // 0..2047
    const int tid = threadIdx.x;

    __shared__ float4 Ksm[BKV][16];
    __shared__ float4 Vsm[BKV][16];

    // Q row into registers
    float qreg[64];
    {
        const float* qrow = g_Q + ((size_t)(b * L_ + q_idx)) * D_ + h * HD_;
        #pragma unroll
        for (int c = 0; c < 16; c++) {
            float4 t = *(const float4*)(qrow + 4 * c);
            qreg[4*c] = t.x; qreg[4*c+1] = t.y; qreg[4*c+2] = t.z; qreg[4*c+3] = t.w;
        }
    }

    float acc[64];
    #pragma unroll
    for (int d = 0; d < 64; d++) acc[d] = 0.f;
    float m = -CUDART_INF_F;
    float l = 0.f;

    for (int j0 = 0; j0 < L_; j0 += BKV) {
        // Stage K/V tile: 32 rows x 64 floats = 512 float4 each, 4 per thread
        #pragma unroll
        for (int p = 0; p < 4; p++) {
            int idx = tid + p * 128;
            int row = idx >> 4;
            int c   = idx & 15;
            size_t base = ((size_t)(b * L_ + j0 + row)) * D_ + h * HD_ + 4 * c;
            Ksm[row][c] = *(const float4*)(g_K + base);
            Vsm[row][c] = *(const float4*)(g_V + base);
        }
        __syncthreads();

        // Scores for this tile
        float s[BKV];
        float tmax = -CUDART_INF_F;
        #pragma unroll
        for (int ki = 0; ki < BKV; ki++) {
            float a0 = 0.f, a1 = 0.f, a2 = 0.f, a3 = 0.f;
            #pragma unroll
            for (int c = 0; c < 16; c++) {
                float4 kv = Ksm[ki][c];
                a0 = fmaf(qreg[4*c],   kv.x, a0);
                a1 = fmaf(qreg[4*c+1], kv.y, a1);
                a2 = fmaf(qreg[4*c+2], kv.z, a2);
                a3 = fmaf(qreg[4*c+3], kv.w, a3);
            }
            float dot = (a0 + a1) + (a2 + a3);
            float sc = fmaf(dot, SCALE, (float)(q_idx - (j0 + ki)));
            s[ki] = sc;
            tmax = fmaxf(tmax, sc);
        }

        // Online softmax update
        float m_new = fmaxf(m, tmax);
        float corr = __expf(m - m_new);
        l *= corr;
        #pragma unroll
        for (int d = 0; d < 64; d++) acc[d] *= corr;

        #pragma unroll
        for (int ki = 0; ki < BKV; ki++) {
            float p = __expf(s[ki] - m_new);
            l += p;
            #pragma unroll
            for (int c = 0; c < 16; c++) {
                float4 vv = Vsm[ki][c];
                acc[4*c]   = fmaf(p, vv.x, acc[4*c]);
                acc[4*c+1] = fmaf(p, vv.y, acc[4*c+1]);
                acc[4*c+2] = fmaf(p, vv.z, acc[4*c+2]);
                acc[4*c+3] = fmaf(p, vv.w, acc[4*c+3]);
            }
        }
        m = m_new;
        __syncthreads();
    }

    const float inv = 1.f / l;
    float* orow = out + ((size_t)(b * L_ + q_idx)) * D_ + h * HD_;
    #pragma unroll
    for (int c = 0; c < 16; c++) {
        float4 t = make_float4(acc[4*c] * inv, acc[4*c+1] * inv,
                               acc[4*c+2] * inv, acc[4*c+3] * inv);
        *(float4*)(orow + 4 * c) = t;
    }
}

// ---------------------------------------------------------------------------
extern "C" void kernel_launch(void* const* d_in, const int* in_sizes, int n_in,
                              void* d_out, int out_size)
{
    const float* q  = (const float*)d_in[0];
    const float* k  = (const float*)d_in[1];
    const float* v  = (const float*)d_in[2];
    const float* Wq = (const float*)d_in[3];
    const float* Wk = (const float*)d_in[4];
    const float* Wv = (const float*)d_in[5];
    float* out = (float*)d_out;

    dim3 ggrid(D_ / GBN, NTOK / GBM, 3);   // (8, 32, 3)
    proj_gemm<<<ggrid, 256>>>(q, k, v, Wq, Wk, Wv);

    dim3 agrid(L_ / 128, H_, B_);          // (16, 16, 2)
    flash_attn<<<agrid, 128>>>(out);
}